// round 16
// baseline (speedup 1.0000x reference)
#include <cuda_runtime.h>

// Quaternion power unit — lane=token + channel-split warp pairs.
//   Warp pair per out-pair: warp A folds channels [0,32), warp B [32,64),
//   each as dual 16-channel Hamilton chains (packed f32x2, 2 outputs/thread,
//   MUFU-free poly sincos). B posts its partial to smem; A merges in order,
//   normalizes, stores. Doubles resident warps vs R11 (4096 -> 8192).

#define CIN 64
#define COUT 128
#define TOK_PER_BLK 32
#define OPP_PER_BLK 4     // out-pairs per block (one per warp PAIR)
#define NTHREADS 256      // 8 warps = 4 opairs x 2 channel-halves

typedef unsigned long long u64;

__device__ __forceinline__ u64 pk2(float lo, float hi) {
    u64 r; asm("mov.b64 %0, {%1, %2};" : "=l"(r) : "f"(lo), "f"(hi)); return r;
}
__device__ __forceinline__ void up2(u64 v, float& lo, float& hi) {
    asm("mov.b64 {%0, %1}, %2;" : "=f"(lo), "=f"(hi) : "l"(v));
}
__device__ __forceinline__ u64 f2fma(u64 a, u64 b, u64 c) {
    u64 d; asm("fma.rn.f32x2 %0, %1, %2, %3;" : "=l"(d) : "l"(a), "l"(b), "l"(c)); return d;
}
__device__ __forceinline__ u64 f2mul(u64 a, u64 b) {
    u64 d; asm("mul.rn.f32x2 %0, %1, %2;" : "=l"(d) : "l"(a), "l"(b)); return d;
}

#define SGNC 0x8000000080000000ull

// acc = acc (x) q  (Hamilton, acc on the left)
__device__ __forceinline__ void ham(u64& ar, u64& ai, u64& aj, u64& ak,
                                    u64 qr, u64 qi, u64 qj, u64 qk) {
    u64 nr = f2fma(ar, qr, f2fma(ai, qi ^ SGNC, f2fma(aj, qj ^ SGNC, f2mul(ak, qk ^ SGNC))));
    u64 ni = f2fma(ar, qi, f2fma(ai, qr,        f2fma(aj, qk,        f2mul(ak, qj ^ SGNC))));
    u64 nj = f2fma(ar, qj, f2fma(ai, qk ^ SGNC, f2fma(aj, qr,        f2mul(ak, qi))));
    u64 nk = f2fma(ar, qk, f2fma(ai, qj,        f2fma(aj, qi ^ SGNC, f2mul(ak, qr))));
    ar = nr; ai = ni; aj = nj; ak = nk;
}

struct PolyC { u64 S1, S2, S3, C1, C2, C3, C4, ONE; };

__device__ __forceinline__ void mkq(float4 d, u64 w2, u64 bias2, const PolyC& P,
                                    u64& qr, u64& qi, u64& qj, u64& qk) {
    u64 th = f2fma(w2, pk2(d.x, d.x), bias2);
    u64 y  = f2mul(th, th);
    u64 p  = f2fma(y, P.S3, P.S2);
    p      = f2fma(y, p, P.S1);
    p      = f2fma(y, p, P.ONE);
    u64 s2 = f2mul(th, p);
    u64 q  = f2fma(y, P.C4, P.C3);
    q      = f2fma(y, q, P.C2);
    q      = f2fma(y, q, P.C1);
    qr     = f2fma(y, q, P.ONE);
    qi = f2mul(pk2(d.y, d.y), s2);
    qj = f2mul(pk2(d.z, d.z), s2);
    qk = f2mul(pk2(d.w, d.w), s2);
}

__global__ __launch_bounds__(NTHREADS, 4)
void qpu_kernel(const float* __restrict__ x, const float* __restrict__ w,
                const float* __restrict__ bias, float* __restrict__ out,
                int n_tokens)
{
    __shared__ __align__(16) float4 tokv[CIN][TOK_PER_BLK + 1];    // ~33.8 KB
    __shared__ __align__(16) u64 swt[OPP_PER_BLK][CIN];            // 2 KB
    // partials posted by half-1 warps: [opair-in-block][lane] = {r,i,j,k}
    __shared__ __align__(16) u64 pbuf[OPP_PER_BLK][TOK_PER_BLK][4]; // 4 KB

    const int tid  = threadIdx.x;
    const int lane = tid & 31;
    const int wp   = tid >> 5;      // 0..7
    const int m    = wp >> 1;       // opair index in block, 0..3
    const int half = wp & 1;        // channel half

    const int tokBase = (blockIdx.x >> 4) * TOK_PER_BLK;
    const int opBase  = (blockIdx.x & 15) * OPP_PER_BLK;
    const int opair   = opBase + m;

    // ---- stage weights: one u64 entry per thread (4 opairs x 64 ch = 256) ----
    {
        int mm = tid >> 6, c = tid & 63;
        int op = opBase + mm;
        swt[mm][c] = pk2(w[(2 * op) * CIN + c], w[(2 * op + 1) * CIN + c]);
    }

    // ---- stage token data: 2048 entries, 8 per thread, coalesced ----
    for (int idx = tid; idx < TOK_PER_BLK * CIN; idx += NTHREADS) {
        int tk = idx >> 6;
        int c  = idx & 63;
        int token = tokBase + tk;
        if (token < n_tokens) {
            const float* xp = x + (size_t)token * (4 * CIN);
            float r = xp[c];
            float i = xp[CIN + c];
            float j = xp[2 * CIN + c];
            float k = xp[3 * CIN + c];
            float inv = rsqrtf(fmaf(i, i, fmaf(j, j, fmaf(k, k, 1e-12f))));
            const float CLAMP = (float)(1.0 - 1e-6);
            r = fminf(fmaxf(r, -CLAMP), CLAMP);
            tokv[c][tk] = make_float4(acosf(r), i * inv, j * inv, k * inv);
        }
    }
    __syncthreads();

    const int token = tokBase + lane;

    PolyC P;
    P.S1 = pk2(-1.6666667e-1f, -1.6666667e-1f);
    P.S2 = pk2( 8.3333333e-3f,  8.3333333e-3f);
    P.S3 = pk2(-1.9841270e-4f, -1.9841270e-4f);
    P.C1 = pk2(-0.5f, -0.5f);
    P.C2 = pk2( 4.1666667e-2f,  4.1666667e-2f);
    P.C3 = pk2(-1.3888889e-3f, -1.3888889e-3f);
    P.C4 = pk2( 2.4801587e-5f,  2.4801587e-5f);
    P.ONE = pk2(1.0f, 1.0f);

    const u64 bias2 = ((const u64*)bias)[opair];   // warp-uniform

    // dual chains over this warp's 32 channels: [cb,cb+16) and [cb+16,cb+32)
    u64 a0r = P.ONE, a0i = 0ull, a0j = 0ull, a0k = 0ull;
    u64 a1r = P.ONE, a1i = 0ull, a1j = 0ull, a1k = 0ull;
    const int cb = half << 5;

#pragma unroll 4
    for (int t = 0; t < 16; ++t) {
        float4 d0 = tokv[cb + t][lane];
        float4 d1 = tokv[cb + 16 + t][lane];
        u64 w0 = swt[m][cb + t];        // uniform
        u64 w1 = swt[m][cb + 16 + t];   // uniform

        u64 qr, qi, qj, qk;
        mkq(d0, w0, bias2, P, qr, qi, qj, qk);
        ham(a0r, a0i, a0j, a0k, qr, qi, qj, qk);

        mkq(d1, w1, bias2, P, qr, qi, qj, qk);
        ham(a1r, a1i, a1j, a1k, qr, qi, qj, qk);
    }

    // merge local chains (in channel order)
    ham(a0r, a0i, a0j, a0k, a1r, a1i, a1j, a1k);

    // ---- cross-warp merge: half 1 posts partial, half 0 combines ----
    if (half == 1) {
        pbuf[m][lane][0] = a0r;
        pbuf[m][lane][1] = a0i;
        pbuf[m][lane][2] = a0j;
        pbuf[m][lane][3] = a0k;
    }
    __syncthreads();

    if (half == 0 && token < n_tokens) {
        u64 br = pbuf[m][lane][0];
        u64 bi = pbuf[m][lane][1];
        u64 bj = pbuf[m][lane][2];
        u64 bk = pbuf[m][lane][3];
        ham(a0r, a0i, a0j, a0k, br, bi, bj, bk);   // P = C[0,32) (x) C[32,64)

        u64 eps2 = pk2(1e-12f, 1e-12f);
        u64 n2 = f2fma(a0r, a0r, f2fma(a0i, a0i, f2fma(a0j, a0j, f2fma(a0k, a0k, eps2))));
        float n0, n1; up2(n2, n0, n1);
        u64 inv2 = pk2(rsqrtf(n0), rsqrtf(n1));

        u64 v0 = f2mul(a0r, inv2);
        u64 v1 = f2mul(a0i, inv2);
        u64 v2 = f2mul(a0j, inv2);
        u64 v3 = f2mul(a0k, inv2);

        float2* ob = (float2*)(out + (size_t)token * (4 * COUT));
        ob[opair]        = *(float2*)&v0;   // pr
        ob[64 + opair]   = *(float2*)&v1;   // pi
        ob[128 + opair]  = *(float2*)&v2;   // pj
        ob[192 + opair]  = *(float2*)&v3;   // pk
    }
}

extern "C" void kernel_launch(void* const* d_in, const int* in_sizes, int n_in,
                              void* d_out, int out_size) {
    const float* x = (const float*)d_in[0];
    const float* w = (const float*)d_in[1];
    const float* b = (const float*)d_in[2];
    int tokens = in_sizes[0] / (4 * CIN);
    int tokBlocks = (tokens + TOK_PER_BLK - 1) / TOK_PER_BLK;
    int grid = tokBlocks * 16;   // 16 opair-groups of 4 (64 out-pairs total)
    qpu_kernel<<<grid, NTHREADS>>>(x, w, b, (float*)d_out, tokens);
}